// round 6
// baseline (speedup 1.0000x reference)
#include <cuda_runtime.h>
#include <cuda_bf16.h>
#include <cuda_fp16.h>
#include <stdint.h>

#define NB     4096
#define NROWS  8192
#define DD     128
#define BM     128
#define BN     128
#define JSPLIT 4
#define JT     (NROWS / JSPLIT / BN)   // 16
#define LDSTR  136                      // fallback smem stride

// tcgen05 only exists in the arch-specific (sm_103a/sm_100a) compilation pass.
#if !defined(__CUDA_ARCH__) || defined(__CUDA_ARCH_FEAT_SM103_ALL) || \
    defined(__CUDA_ARCH_FEAT_SM100_ALL) || defined(__CUDA_ARCH_SPECIFIC__) || \
    defined(__CUDA_ARCH_FAMILY_SPECIFIC__)
#define HAS_TC 1
#else
#define HAS_TC 0
#endif

__device__ __align__(16) __nv_bfloat16  d_zb[NROWS * DD];
__device__ float  d_S  [NROWS];
__device__ float  d_pos[NB];
__device__ double d_total;

// ------------------------------------------------------------------ utils
__device__ __forceinline__ uint32_t smem_u32(const void* p) {
    uint32_t a;
    asm("{ .reg .u64 t; cvta.to.shared.u64 t, %1; cvt.u32.u64 %0, t; }"
        : "=r"(a) : "l"(p));
    return a;
}
__device__ __forceinline__ float ex2f(float x) {
    float y; asm("ex2.approx.ftz.f32 %0, %1;" : "=f"(y) : "f"(x)); return y;
}

// ------------------------------------------------------------------ normalize (+zero S/total)
__global__ void normalize_kernel(const float* __restrict__ xi,
                                 const float* __restrict__ xj) {
    int t = blockIdx.x * blockDim.x + threadIdx.x;
    if (t < NROWS) d_S[t] = 0.0f;
    if (t == 0) d_total = 0.0;
    int warp = t >> 5;
    int lane = threadIdx.x & 31;
    if (warp >= NROWS) return;
    const float* src = (warp < NB) ? (xi + (size_t)warp * DD)
                                   : (xj + (size_t)(warp - NB) * DD);
    float4 v = ((const float4*)src)[lane];
    float s = v.x*v.x + v.y*v.y + v.z*v.z + v.w*v.w;
    #pragma unroll
    for (int o = 16; o; o >>= 1) s += __shfl_xor_sync(0xffffffffu, s, o);
    float inv = 1.0f / fmaxf(sqrtf(s), 1e-12f);
    __nv_bfloat162* zb = (__nv_bfloat162*)(d_zb + (size_t)warp * DD);
    zb[lane*2 + 0] = __floats2bfloat162_rn(v.x*inv, v.y*inv);
    zb[lane*2 + 1] = __floats2bfloat162_rn(v.z*inv, v.w*inv);
}

// ------------------------------------------------------------------ positives (fp32 from bf16 z)
__global__ void pos_kernel() {
    int warp = (blockIdx.x * blockDim.x + threadIdx.x) >> 5;
    int lane = threadIdx.x & 31;
    if (warp >= NB) return;
    const uint2* pa = (const uint2*)(d_zb + (size_t)warp        * DD);
    const uint2* pb = (const uint2*)(d_zb + (size_t)(warp + NB) * DD);
    uint2 ua = pa[lane], ub = pb[lane];
    float2 a0 = __bfloat1622float2(*(__nv_bfloat162*)&ua.x);
    float2 a1 = __bfloat1622float2(*(__nv_bfloat162*)&ua.y);
    float2 b0 = __bfloat1622float2(*(__nv_bfloat162*)&ub.x);
    float2 b1 = __bfloat1622float2(*(__nv_bfloat162*)&ub.y);
    float s = a0.x*b0.x + a0.y*b0.y + a1.x*b1.x + a1.y*b1.y;
    #pragma unroll
    for (int o = 16; o; o >>= 1) s += __shfl_xor_sync(0xffffffffu, s, o);
    if (lane == 0) d_pos[warp] = s;
}

// ================================================================== tcgen05 path
#if HAS_TC
#define DESC_BASE ((2ull << 61) | (1ull << 46) | (64ull << 32) | (1ull << 16))
__device__ __forceinline__ uint64_t make_desc(uint32_t addr) {
    return DESC_BASE | ((uint64_t)(addr >> 4) & 0x3FFF);
}
// idesc kind::f16: dtype=F32, a=BF16, b=BF16 (K-major), N=128, M=128 (proven)
#define MMA_IDESC 0x8200490u

__device__ __forceinline__ void mma_f16_ss(uint32_t d, uint64_t a, uint64_t b,
                                           uint32_t en) {
    asm volatile(
        "{\n\t.reg .pred p;\n\t"
        "setp.ne.u32 p, %4, 0;\n\t"
        "tcgen05.mma.cta_group::1.kind::f16 [%0], %1, %2, %3, {%5,%5,%5,%5}, p;\n\t}"
        :: "r"(d), "l"(a), "l"(b), "r"(MMA_IDESC), "r"(en), "r"(0u) : "memory");
}

#define MBAR_INIT(a)   asm volatile("mbarrier.init.shared.b64 [%0], 1;" :: "r"(a) : "memory")
#define MBAR_INVAL(a)  asm volatile("mbarrier.inval.shared.b64 [%0];"   :: "r"(a) : "memory")
#define TC_COMMIT(a)   asm volatile("tcgen05.commit.cta_group::1.mbarrier::arrive::one.shared::cluster.b64 [%0];" :: "r"(a) : "memory")
#define TC_FENCE_AFTER()  asm volatile("tcgen05.fence::after_thread_sync;"  ::: "memory")
#define TC_FENCE_BEFORE() asm volatile("tcgen05.fence::before_thread_sync;" ::: "memory")
#define TC_WAIT_LD()      asm volatile("tcgen05.wait::ld.sync.aligned;"     ::: "memory")
#define FENCE_ASYNC()     asm volatile("fence.proxy.async.shared::cta;"     ::: "memory")

__device__ __forceinline__ void mbar_wait(uint32_t mbar, uint32_t parity) {
    uint32_t done;
    asm volatile(
        "{\n\t.reg .pred p;\n\t"
        "mbarrier.try_wait.parity.acquire.cta.shared::cta.b64 p, [%1], %2;\n\t"
        "selp.b32 %0, 1, 0, p;\n\t}"
        : "=r"(done) : "r"(mbar), "r"(parity) : "memory");
    if (!done) {
        asm volatile(
            "{\n\t.reg .pred P1;\n\t"
            "WL_%=:\n\t"
            "mbarrier.try_wait.parity.acquire.cta.shared::cta.b64 P1, [%0], %1, 0x989680;\n\t"
            "@P1 bra.uni WD_%=;\n\t"
            "bra.uni WL_%=;\n\t"
            "WD_%=:\n\t}"
            :: "r"(mbar), "r"(parity) : "memory");
    }
}

#define LDTM_X32(r, a) \
    asm volatile("tcgen05.ld.sync.aligned.32x32b.x32.b32 " \
        "{%0,%1,%2,%3,%4,%5,%6,%7,%8,%9,%10,%11,%12,%13,%14,%15," \
        "%16,%17,%18,%19,%20,%21,%22,%23,%24,%25,%26,%27,%28,%29,%30,%31}, [%32];" \
        : "=r"((r)[0]),"=r"((r)[1]),"=r"((r)[2]),"=r"((r)[3]), \
          "=r"((r)[4]),"=r"((r)[5]),"=r"((r)[6]),"=r"((r)[7]), \
          "=r"((r)[8]),"=r"((r)[9]),"=r"((r)[10]),"=r"((r)[11]), \
          "=r"((r)[12]),"=r"((r)[13]),"=r"((r)[14]),"=r"((r)[15]), \
          "=r"((r)[16]),"=r"((r)[17]),"=r"((r)[18]),"=r"((r)[19]), \
          "=r"((r)[20]),"=r"((r)[21]),"=r"((r)[22]),"=r"((r)[23]), \
          "=r"((r)[24]),"=r"((r)[25]),"=r"((r)[26]),"=r"((r)[27]), \
          "=r"((r)[28]),"=r"((r)[29]),"=r"((r)[30]),"=r"((r)[31]) \
        : "r"(a))
#endif  // HAS_TC

// blocked-atom SW128 byte offset for (row, 16B-chunk) of a 128x128 bf16 tile
__device__ __forceinline__ uint32_t tile_off(int row, int c16) {
    uint32_t byte = (uint32_t)(((row >> 3) + ((c16 >> 3) << 4)) * 1024
                               + (row & 7) * 128 + (c16 & 7) * 16);
    return byte ^ ((byte >> 3) & 0x70);
}

#if !HAS_TC
__device__ __forceinline__ void mma16816(float c[4], const uint32_t a[4],
                                         const uint32_t b[2]) {
    asm volatile(
        "mma.sync.aligned.m16n8k16.row.col.f32.bf16.bf16.f32 "
        "{%0,%1,%2,%3}, {%4,%5,%6,%7}, {%8,%9}, {%0,%1,%2,%3};\n"
        : "+f"(c[0]), "+f"(c[1]), "+f"(c[2]), "+f"(c[3])
        : "r"(a[0]), "r"(a[1]), "r"(a[2]), "r"(a[3]), "r"(b[0]), "r"(b[1]));
}
#endif

// smem: [0] tmem ptr, [8..24) mbar[2], [1024) A 32KB, [+32K) B0, B1
#define S_OFF_A   1024
#define S_OFF_B0  (S_OFF_A + 32768)
#define SMEM_TOT  (S_OFF_B0 + 2 * 32768)

__global__ void __launch_bounds__(256, 2) sim_kernel() {
    extern __shared__ __align__(1024) char smem[];
    const int tid   = threadIdx.x;
    const int ibase = blockIdx.x * BM;
    const int j0    = blockIdx.y * (NROWS / JSPLIT);

#if HAS_TC
    const uint32_t sb = smem_u32(smem);
    const int w    = tid >> 5, lane = tid & 31;
    const int sp   = w & 3, half = w >> 2;
    const int rg   = ibase + sp * 32 + lane;
    const float Cf = 14.4269504088896340737f;   // (1/T) * log2(e)
    uint32_t cf2;
    { __half2 h2 = __float2half2_rn(Cf); cf2 = *(uint32_t*)&h2; }
    uint32_t z16;
    { __half2 z2 = __float2half2_rn(0.f); z16 = *(uint32_t*)&z2; }

    if (w == 0)
        asm volatile("tcgen05.alloc.cta_group::1.sync.aligned.shared::cta.b32 [%0], 256;"
                     :: "r"(sb) : "memory");
    if (tid == 0) { MBAR_INIT(sb + 8); MBAR_INIT(sb + 16); }
    __syncthreads();
    uint32_t tmem;
    asm volatile("ld.shared.b32 %0, [%1];" : "=r"(tmem) : "r"(sb));

    // A tile + B tile0 together (max MLP)
    for (int c = tid; c < 4096; c += 256) {
        int half_sel = c >> 11;            // 0: A, 1: B0
        int idx = c & 2047;
        int row = idx >> 4, c16 = idx & 15;
        int src_row = (half_sel ? j0 : ibase) + row;
        uint4 v = *(const uint4*)(d_zb + (size_t)src_row * DD + c16 * 8);
        *(uint4*)(smem + (half_sel ? S_OFF_B0 : S_OFF_A) + tile_off(row, c16)) = v;
    }
    FENCE_ASYNC();
    __syncthreads();
    const uint64_t a_desc = make_desc(sb + S_OFF_A);
    if (tid == 0) {
        const uint64_t b_desc = make_desc(sb + S_OFF_B0);
        #pragma unroll
        for (int k = 0; k < 8; k++) {
            uint32_t off = (k < 4) ? 2u * k : 1024u + 2u * (k - 4);
            mma_f16_ss(tmem, a_desc + off, b_desc + off, k > 0);
        }
        TC_COMMIT(sb + 8);
    }
    // B tile1 into buffer 1 (while MMA(0) runs)
    for (int c = tid; c < 2048; c += 256) {
        int row = c >> 4, c16 = c & 15;
        uint4 v = *(const uint4*)(d_zb + (size_t)(j0 + BN + row) * DD + c16 * 8);
        *(uint4*)(smem + S_OFF_B0 + 32768 + tile_off(row, c16)) = v;
    }
    FENCE_ASYNC();

    float rowsum = 0.0f;

    for (int jt = 1; jt <= JT; ++jt) {
        const int p = jt & 1, q = p ^ 1;

        // 1. prefetch tile jt+1 into registers (hidden under wait + epilogue)
        uint4 pf[8];
        const bool do_pf = (jt + 1 < JT);
        if (do_pf) {
            const int jb = j0 + (jt + 1) * BN;
            #pragma unroll
            for (int u = 0; u < 8; u++) {
                int c = tid + u * 256;
                int row = c >> 4, c16 = c & 15;
                pf[u] = *(const uint4*)(d_zb + (size_t)(jb + row) * DD + c16 * 8);
            }
        }

        // 2. wait MMA(jt-1) done
        mbar_wait(sb + 8 + q * 8, ((jt - 1) >> 1) & 1);
        TC_FENCE_AFTER();
        // 3. all LDTMs of D[p] (tile jt-2) done; B[p] stores visible
        __syncthreads();

        // 4. issue MMA(jt)
        if (jt < JT && tid == 0) {
            const uint64_t b_desc = make_desc(sb + S_OFF_B0 + p * 32768);
            const uint32_t dtm = tmem + p * 128;
            #pragma unroll
            for (int k = 0; k < 8; k++) {
                uint32_t off = (k < 4) ? 2u * k : 1024u + 2u * (k - 4);
                mma_f16_ss(dtm, a_desc + off, b_desc + off, k > 0);
            }
            TC_COMMIT(sb + 8 + p * 8);
        }

        // 5. epilogue of tile jt-1 from D[q]
        const int jb1 = j0 + (jt - 1) * BN;
        const uint32_t taddr = tmem + q * 128 + ((uint32_t)sp << 21) + half * 64;
        if (jb1 != ibase) {
            #pragma unroll
            for (int h = 0; h < 2; h++) {
                uint32_t r[32];
                LDTM_X32(r, taddr + h * 32);
                TC_WAIT_LD();
                uint32_t a0 = z16, a1 = z16;
                #pragma unroll
                for (int j = 0; j < 32; j += 4) {
                    uint32_t hh, e;
                    asm("cvt.rn.f16x2.f32 %0, %1, %2;" : "=r"(hh)
                        : "f"(__uint_as_float(r[j + 1])), "f"(__uint_as_float(r[j])));
                    asm("mul.f16x2 %0, %1, %2;" : "=r"(hh) : "r"(hh), "r"(cf2));
                    asm("ex2.approx.f16x2 %0, %1;" : "=r"(e) : "r"(hh));
                    asm("add.f16x2 %0, %1, %2;" : "=r"(a0) : "r"(a0), "r"(e));
                    asm("cvt.rn.f16x2.f32 %0, %1, %2;" : "=r"(hh)
                        : "f"(__uint_as_float(r[j + 3])), "f"(__uint_as_float(r[j + 2])));
                    asm("mul.f16x2 %0, %1, %2;" : "=r"(hh) : "r"(hh), "r"(cf2));
                    asm("ex2.approx.f16x2 %0, %1;" : "=r"(e) : "r"(hh));
                    asm("add.f16x2 %0, %1, %2;" : "=r"(a1) : "r"(a1), "r"(e));
                }
                float2 f0 = __half22float2(*(__half2*)&a0);
                float2 f1 = __half22float2(*(__half2*)&a1);
                rowsum += (f0.x + f0.y) + (f1.x + f1.y);
            }
        } else {
            // diagonal tile: exact f32 path with masking
            const int dcol = rg - jb1 - half * 64;
            #pragma unroll
            for (int h = 0; h < 2; h++) {
                uint32_t r[32];
                LDTM_X32(r, taddr + h * 32);
                TC_WAIT_LD();
                float s0 = 0.f;
                #pragma unroll
                for (int j = 0; j < 32; j++) {
                    float e = ex2f(__uint_as_float(r[j]) * Cf);
                    if (j + h * 32 != dcol) s0 += e;
                }
                rowsum += s0;
            }
        }
        TC_FENCE_BEFORE();

        // 6. store prefetched tile jt+1 into freed B[q]
        if (do_pf) {
            #pragma unroll
            for (int u = 0; u < 8; u++) {
                int c = tid + u * 256;
                int row = c >> 4, c16 = c & 15;
                *(uint4*)(smem + S_OFF_B0 + q * 32768 + tile_off(row, c16)) = pf[u];
            }
            FENCE_ASYNC();
        }
    }

    atomicAdd(&d_S[rg], rowsum);

    __syncthreads();
    if (tid == 0) { MBAR_INVAL(sb + 8); MBAR_INVAL(sb + 16); }
    __syncthreads();
    if (w == 0) {
        asm volatile("tcgen05.relinquish_alloc_permit.cta_group::1.sync.aligned;");
        asm volatile("tcgen05.dealloc.cta_group::1.sync.aligned.b32 %0, 256;"
                     :: "r"(tmem));
    }
#else
    // ---------------- HMMA fallback (plain sm_103 pass; never runs on GB300) ------
    __nv_bfloat16* As = (__nv_bfloat16*)smem;
    __nv_bfloat16* Bs = As + BM * LDSTR;

    const int wid    = tid >> 5;
    const int lane   = tid & 31;
    const int g      = lane >> 2;
    const int q      = lane & 3;
    const int warp_m = wid & 3;
    const int warp_n = wid >> 2;

    for (int c = tid; c < BM * DD / 8; c += 256) {
        int row = c >> 4, c8 = c & 15;
        *(uint4*)(As + row * LDSTR + c8 * 8) =
            *(const uint4*)(d_zb + (size_t)(ibase + row) * DD + c8 * 8);
    }

    float rowsum[2][2] = {{0.f, 0.f}, {0.f, 0.f}};

    for (int jt = 0; jt < JT; ++jt) {
        const int jbase = j0 + jt * BN;
        __syncthreads();
        for (int c = tid; c < BN * DD / 8; c += 256) {
            int row = c >> 4, c8 = c & 15;
            *(uint4*)(Bs + row * LDSTR + c8 * 8) =
                *(const uint4*)(d_zb + (size_t)(jbase + row) * DD + c8 * 8);
        }
        __syncthreads();

        float acc[2][8][4];
        #pragma unroll
        for (int mf = 0; mf < 2; mf++)
            #pragma unroll
            for (int nf = 0; nf < 8; nf++)
                #pragma unroll
                for (int e = 0; e < 4; e++) acc[mf][nf][e] = 0.f;

        #pragma unroll
        for (int kk = 0; kk < 8; kk++) {
            const int kb = kk * 16;
            uint32_t a[2][4], b[8][2];
            #pragma unroll
            for (int mf = 0; mf < 2; mf++) {
                const __nv_bfloat16* pp =
                    As + (warp_m * 32 + mf * 16 + g) * LDSTR + kb + 2 * q;
                a[mf][0] = *(const uint32_t*)pp;
                a[mf][1] = *(const uint32_t*)(pp + 8 * LDSTR);
                a[mf][2] = *(const uint32_t*)(pp + 8);
                a[mf][3] = *(const uint32_t*)(pp + 8 * LDSTR + 8);
            }
            #pragma unroll
            for (int nf = 0; nf < 8; nf++) {
                const __nv_bfloat16* pp =
                    Bs + (warp_n * 64 + nf * 8 + g) * LDSTR + kb + 2 * q;
                b[nf][0] = *(const uint32_t*)pp;
                b[nf][1] = *(const uint32_t*)(pp + 8);
            }
            #pragma unroll
            for (int mf = 0; mf < 2; mf++)
                #pragma unroll
                for (int nf = 0; nf < 8; nf++)
                    mma16816(acc[mf][nf], a[mf], b[nf]);
        }

        #pragma unroll
        for (int mf = 0; mf < 2; mf++)
            #pragma unroll
            for (int nf = 0; nf < 8; nf++)
                #pragma unroll
                for (int e = 0; e < 4; e++) {
                    int rgl = ibase + warp_m * 32 + mf * 16 + g + ((e >> 1) << 3);
                    int cg  = jbase + warp_n * 64 + nf * 8 + q * 2 + (e & 1);
                    float ev = (rgl == cg) ? 0.f : __expf(acc[mf][nf][e] * 10.0f);
                    rowsum[mf][e >> 1] += ev;
                }
    }

    #pragma unroll
    for (int mf = 0; mf < 2; mf++)
        #pragma unroll
        for (int h = 0; h < 2; h++) {
            float s = rowsum[mf][h];
            s += __shfl_xor_sync(0xffffffffu, s, 1);
            s += __shfl_xor_sync(0xffffffffu, s, 2);
            if (q == 0)
                atomicAdd(&d_S[ibase + warp_m * 32 + mf * 16 + g + h * 8], s);
        }
#endif
}

// ------------------------------------------------------------------ final reduce
__global__ void reduceA_kernel() {
    const int i = blockIdx.x * 256 + threadIdx.x;
    double s = (double)__logf(d_S[i]);
    if (threadIdx.x < 128) s -= 20.0 * (double)d_pos[blockIdx.x * 128 + threadIdx.x];
    #pragma unroll
    for (int o = 16; o; o >>= 1) s += __shfl_xor_sync(0xffffffffu, s, o);
    if ((threadIdx.x & 31) == 0) atomicAdd(&d_total, s);
}

__global__ void reduceC_kernel(float* out) {
    out[0] = (float)(d_total / (double)NROWS);
}

// ------------------------------------------------------------------ launch
extern "C" void kernel_launch(void* const* d_in, const int* in_sizes, int n_in,
                              void* d_out, int out_size) {
    const float* xi = (const float*)d_in[0];
    const float* xj = (const float*)d_in[1];
    float* out = (float*)d_out;

    cudaFuncSetAttribute(sim_kernel,
                         cudaFuncAttributeMaxDynamicSharedMemorySize, SMEM_TOT);

    normalize_kernel<<<NROWS / 8, 256>>>(xi, xj);
    pos_kernel<<<NB / 8, 256>>>();
    dim3 grid(NROWS / BM, JSPLIT);
    sim_kernel<<<grid, 256, SMEM_TOT>>>();
    reduceA_kernel<<<32, 256>>>();
    reduceC_kernel<<<1, 1>>>(out);
}

// round 7
// speedup vs baseline: 1.4300x; 1.4300x over previous
#include <cuda_runtime.h>
#include <cuda_bf16.h>
#include <cuda_fp16.h>
#include <stdint.h>

#define NB     4096
#define NROWS  8192
#define DD     128
#define BM     128
#define BN     128
#define JSPLIT 4
#define JT     (NROWS / JSPLIT / BN)   // 16
#define NBLK   ((NROWS / BM) * JSPLIT) // 256
#define LDSTR  136                      // fallback smem stride

// tcgen05 only exists in the arch-specific (sm_103a/sm_100a) compilation pass.
#if !defined(__CUDA_ARCH__) || defined(__CUDA_ARCH_FEAT_SM103_ALL) || \
    defined(__CUDA_ARCH_FEAT_SM100_ALL) || defined(__CUDA_ARCH_SPECIFIC__) || \
    defined(__CUDA_ARCH_FAMILY_SPECIFIC__)
#define HAS_TC 1
#else
#define HAS_TC 0
#endif

__device__ __align__(16) __nv_bfloat16  d_zb[NROWS * DD];
__device__ float        d_S  [NROWS];
__device__ float        d_pos[NB];
__device__ unsigned int d_count;

// ------------------------------------------------------------------ utils
__device__ __forceinline__ uint32_t smem_u32(const void* p) {
    uint32_t a;
    asm("{ .reg .u64 t; cvta.to.shared.u64 t, %1; cvt.u32.u64 %0, t; }"
        : "=r"(a) : "l"(p));
    return a;
}
__device__ __forceinline__ float ex2f(float x) {
    float y; asm("ex2.approx.ftz.f32 %0, %1;" : "=f"(y) : "f"(x)); return y;
}
__device__ __forceinline__ void cpasync16(uint32_t dst, const void* src) {
    asm volatile("cp.async.cg.shared.global [%0], [%1], 16;"
                 :: "r"(dst), "l"(src) : "memory");
}
#define CP_COMMIT() asm volatile("cp.async.commit_group;" ::: "memory")
#define CP_WAIT0()  asm volatile("cp.async.wait_group 0;" ::: "memory")

// ------------------------------------------------------------------ normalize (+zero S/count)
__global__ void normalize_kernel(const float* __restrict__ xi,
                                 const float* __restrict__ xj) {
    int t = blockIdx.x * blockDim.x + threadIdx.x;
    if (t < NROWS) d_S[t] = 0.0f;
    if (t == 0) d_count = 0u;
    int warp = t >> 5;
    int lane = threadIdx.x & 31;
    if (warp >= NROWS) return;
    const float* src = (warp < NB) ? (xi + (size_t)warp * DD)
                                   : (xj + (size_t)(warp - NB) * DD);
    float4 v = ((const float4*)src)[lane];
    float s = v.x*v.x + v.y*v.y + v.z*v.z + v.w*v.w;
    #pragma unroll
    for (int o = 16; o; o >>= 1) s += __shfl_xor_sync(0xffffffffu, s, o);
    float inv = 1.0f / fmaxf(sqrtf(s), 1e-12f);
    __nv_bfloat162* zb = (__nv_bfloat162*)(d_zb + (size_t)warp * DD);
    zb[lane*2 + 0] = __floats2bfloat162_rn(v.x*inv, v.y*inv);
    zb[lane*2 + 1] = __floats2bfloat162_rn(v.z*inv, v.w*inv);
}

// ------------------------------------------------------------------ positives (fp32 from bf16 z)
__global__ void pos_kernel() {
    int warp = (blockIdx.x * blockDim.x + threadIdx.x) >> 5;
    int lane = threadIdx.x & 31;
    if (warp >= NB) return;
    const uint2* pa = (const uint2*)(d_zb + (size_t)warp        * DD);
    const uint2* pb = (const uint2*)(d_zb + (size_t)(warp + NB) * DD);
    uint2 ua = pa[lane], ub = pb[lane];
    float2 a0 = __bfloat1622float2(*(__nv_bfloat162*)&ua.x);
    float2 a1 = __bfloat1622float2(*(__nv_bfloat162*)&ua.y);
    float2 b0 = __bfloat1622float2(*(__nv_bfloat162*)&ub.x);
    float2 b1 = __bfloat1622float2(*(__nv_bfloat162*)&ub.y);
    float s = a0.x*b0.x + a0.y*b0.y + a1.x*b1.x + a1.y*b1.y;
    #pragma unroll
    for (int o = 16; o; o >>= 1) s += __shfl_xor_sync(0xffffffffu, s, o);
    if (lane == 0) d_pos[warp] = s;
}

// ================================================================== tcgen05 path
#if HAS_TC
#define DESC_BASE ((2ull << 61) | (1ull << 46) | (64ull << 32) | (1ull << 16))
__device__ __forceinline__ uint64_t make_desc(uint32_t addr) {
    return DESC_BASE | ((uint64_t)(addr >> 4) & 0x3FFF);
}
// idesc kind::f16: dtype=F32, a=BF16, b=BF16 (K-major), N=128, M=128 (proven)
#define MMA_IDESC 0x8200490u

__device__ __forceinline__ void mma_f16_ss(uint32_t d, uint64_t a, uint64_t b,
                                           uint32_t en) {
    asm volatile(
        "{\n\t.reg .pred p;\n\t"
        "setp.ne.u32 p, %4, 0;\n\t"
        "tcgen05.mma.cta_group::1.kind::f16 [%0], %1, %2, %3, {%5,%5,%5,%5}, p;\n\t}"
        :: "r"(d), "l"(a), "l"(b), "r"(MMA_IDESC), "r"(en), "r"(0u) : "memory");
}

#define MBAR_INIT(a)   asm volatile("mbarrier.init.shared.b64 [%0], 1;" :: "r"(a) : "memory")
#define MBAR_INVAL(a)  asm volatile("mbarrier.inval.shared.b64 [%0];"   :: "r"(a) : "memory")
#define TC_COMMIT(a)   asm volatile("tcgen05.commit.cta_group::1.mbarrier::arrive::one.shared::cluster.b64 [%0];" :: "r"(a) : "memory")
#define TC_FENCE_AFTER()  asm volatile("tcgen05.fence::after_thread_sync;"  ::: "memory")
#define TC_FENCE_BEFORE() asm volatile("tcgen05.fence::before_thread_sync;" ::: "memory")
#define TC_WAIT_LD()      asm volatile("tcgen05.wait::ld.sync.aligned;"     ::: "memory")
#define FENCE_ASYNC()     asm volatile("fence.proxy.async.shared::cta;"     ::: "memory")

__device__ __forceinline__ void mbar_wait(uint32_t mbar, uint32_t parity) {
    uint32_t done;
    asm volatile(
        "{\n\t.reg .pred p;\n\t"
        "mbarrier.try_wait.parity.acquire.cta.shared::cta.b64 p, [%1], %2;\n\t"
        "selp.b32 %0, 1, 0, p;\n\t}"
        : "=r"(done) : "r"(mbar), "r"(parity) : "memory");
    if (!done) {
        asm volatile(
            "{\n\t.reg .pred P1;\n\t"
            "WL_%=:\n\t"
            "mbarrier.try_wait.parity.acquire.cta.shared::cta.b64 P1, [%0], %1, 0x989680;\n\t"
            "@P1 bra.uni WD_%=;\n\t"
            "bra.uni WL_%=;\n\t"
            "WD_%=:\n\t}"
            :: "r"(mbar), "r"(parity) : "memory");
    }
}

#define LDTM_X32(r, a) \
    asm volatile("tcgen05.ld.sync.aligned.32x32b.x32.b32 " \
        "{%0,%1,%2,%3,%4,%5,%6,%7,%8,%9,%10,%11,%12,%13,%14,%15," \
        "%16,%17,%18,%19,%20,%21,%22,%23,%24,%25,%26,%27,%28,%29,%30,%31}, [%32];" \
        : "=r"((r)[0]),"=r"((r)[1]),"=r"((r)[2]),"=r"((r)[3]), \
          "=r"((r)[4]),"=r"((r)[5]),"=r"((r)[6]),"=r"((r)[7]), \
          "=r"((r)[8]),"=r"((r)[9]),"=r"((r)[10]),"=r"((r)[11]), \
          "=r"((r)[12]),"=r"((r)[13]),"=r"((r)[14]),"=r"((r)[15]), \
          "=r"((r)[16]),"=r"((r)[17]),"=r"((r)[18]),"=r"((r)[19]), \
          "=r"((r)[20]),"=r"((r)[21]),"=r"((r)[22]),"=r"((r)[23]), \
          "=r"((r)[24]),"=r"((r)[25]),"=r"((r)[26]),"=r"((r)[27]), \
          "=r"((r)[28]),"=r"((r)[29]),"=r"((r)[30]),"=r"((r)[31]) \
        : "r"(a))
#endif  // HAS_TC

// blocked-atom SW128 byte offset for (row, 16B-chunk) of a 128x128 bf16 tile
__device__ __forceinline__ uint32_t tile_off(int row, int c16) {
    uint32_t byte = (uint32_t)(((row >> 3) + ((c16 >> 3) << 4)) * 1024
                               + (row & 7) * 128 + (c16 & 7) * 16);
    return byte ^ ((byte >> 3) & 0x70);
}

#if !HAS_TC
__device__ __forceinline__ void mma16816(float c[4], const uint32_t a[4],
                                         const uint32_t b[2]) {
    asm volatile(
        "mma.sync.aligned.m16n8k16.row.col.f32.bf16.bf16.f32 "
        "{%0,%1,%2,%3}, {%4,%5,%6,%7}, {%8,%9}, {%0,%1,%2,%3};\n"
        : "+f"(c[0]), "+f"(c[1]), "+f"(c[2]), "+f"(c[3])
        : "r"(a[0]), "r"(a[1]), "r"(a[2]), "r"(a[3]), "r"(b[0]), "r"(b[1]));
}
#endif

// smem: [0] tmem ptr, [8..24) mbar[2], [1024) A 32KB, [+32K) B0, B1
#define S_OFF_A   1024
#define S_OFF_B0  (S_OFF_A + 32768)
#define SMEM_TOT  (S_OFF_B0 + 2 * 32768)

__global__ void __launch_bounds__(256, 2) sim_kernel(float* __restrict__ out) {
    extern __shared__ __align__(1024) char smem[];
    const int tid   = threadIdx.x;
    const int ibase = blockIdx.x * BM;
    const int j0    = blockIdx.y * (NROWS / JSPLIT);

#if HAS_TC
    const uint32_t sb = smem_u32(smem);
    const int w    = tid >> 5, lane = tid & 31;
    const int sp   = w & 3, half = w >> 2;
    const int rg   = ibase + sp * 32 + lane;
    const float Cf = 14.4269504088896340737f;   // (1/T) * log2(e)
    uint32_t cf2;
    { __half2 h2 = __float2half2_rn(Cf); cf2 = *(uint32_t*)&h2; }
    uint32_t z16;
    { __half2 z2 = __float2half2_rn(0.f); z16 = *(uint32_t*)&z2; }

    // start A + B0 loads immediately (cp.async, no registers held)
    #pragma unroll
    for (int u = 0; u < 8; u++) {
        int c = tid + u * 256;
        int row = c >> 4, c16 = c & 15;
        uint32_t so = tile_off(row, c16);
        cpasync16(sb + S_OFF_A  + so, d_zb + (size_t)(ibase + row) * DD + c16 * 8);
        cpasync16(sb + S_OFF_B0 + so, d_zb + (size_t)(j0    + row) * DD + c16 * 8);
    }
    CP_COMMIT();

    if (w == 0)
        asm volatile("tcgen05.alloc.cta_group::1.sync.aligned.shared::cta.b32 [%0], 256;"
                     :: "r"(sb) : "memory");
    if (tid == 0) { MBAR_INIT(sb + 8); MBAR_INIT(sb + 16); }

    CP_WAIT0();
    FENCE_ASYNC();
    __syncthreads();
    uint32_t tmem;
    asm volatile("ld.shared.b32 %0, [%1];" : "=r"(tmem) : "r"(sb));
    const uint64_t a_desc = make_desc(sb + S_OFF_A);

    // MMA(0) on B0
    if (tid == 0) {
        const uint64_t b_desc = make_desc(sb + S_OFF_B0);
        #pragma unroll
        for (int k = 0; k < 8; k++) {
            uint32_t off = (k < 4) ? 2u * k : 1024u + 2u * (k - 4);
            mma_f16_ss(tmem, a_desc + off, b_desc + off, k > 0);
        }
        TC_COMMIT(sb + 8);
    }
    // prefetch B1 into buf1
    #pragma unroll
    for (int u = 0; u < 8; u++) {
        int c = tid + u * 256;
        int row = c >> 4, c16 = c & 15;
        cpasync16(sb + S_OFF_B0 + 32768 + tile_off(row, c16),
                  d_zb + (size_t)(j0 + BN + row) * DD + c16 * 8);
    }
    CP_COMMIT();

    float rowsum = 0.0f;

    for (int jt = 1; jt <= JT; ++jt) {
        const int p = jt & 1, q = p ^ 1;

        // B(jt) ready in buf p
        if (jt < JT) { CP_WAIT0(); FENCE_ASYNC(); }
        __syncthreads();   // also: epilogue of tile jt-2 (used D[p]) finished

        // issue MMA(jt) into D[p]
        if (jt < JT && tid == 0) {
            const uint64_t b_desc = make_desc(sb + S_OFF_B0 + p * 32768);
            const uint32_t dtm = tmem + p * 128;
            #pragma unroll
            for (int k = 0; k < 8; k++) {
                uint32_t off = (k < 4) ? 2u * k : 1024u + 2u * (k - 4);
                mma_f16_ss(dtm, a_desc + off, b_desc + off, k > 0);
            }
            TC_COMMIT(sb + 8 + p * 8);
        }

        // MMA(jt-1) done -> D[q] ready, buf q free
        mbar_wait(sb + 8 + q * 8, ((jt - 1) >> 1) & 1);
        TC_FENCE_AFTER();

        // prefetch B(jt+1) into freed buf q (background)
        if (jt + 1 < JT) {
            const int jb = j0 + (jt + 1) * BN;
            #pragma unroll
            for (int u = 0; u < 8; u++) {
                int c = tid + u * 256;
                int row = c >> 4, c16 = c & 15;
                cpasync16(sb + S_OFF_B0 + q * 32768 + tile_off(row, c16),
                          d_zb + (size_t)(jb + row) * DD + c16 * 8);
            }
            CP_COMMIT();
        }

        // epilogue of tile jt-1 from D[q]
        const int jb1 = j0 + (jt - 1) * BN;
        const uint32_t taddr = tmem + q * 128 + ((uint32_t)sp << 21) + half * 64;
        if (jb1 != ibase) {
            #pragma unroll
            for (int h = 0; h < 2; h++) {
                uint32_t r[32];
                LDTM_X32(r, taddr + h * 32);
                TC_WAIT_LD();
                uint32_t a0 = z16, a1 = z16;
                #pragma unroll
                for (int j = 0; j < 32; j += 4) {
                    uint32_t hh, e;
                    asm("cvt.rn.f16x2.f32 %0, %1, %2;" : "=r"(hh)
                        : "f"(__uint_as_float(r[j + 1])), "f"(__uint_as_float(r[j])));
                    asm("mul.f16x2 %0, %1, %2;" : "=r"(hh) : "r"(hh), "r"(cf2));
                    asm("ex2.approx.f16x2 %0, %1;" : "=r"(e) : "r"(hh));
                    asm("add.f16x2 %0, %1, %2;" : "=r"(a0) : "r"(a0), "r"(e));
                    asm("cvt.rn.f16x2.f32 %0, %1, %2;" : "=r"(hh)
                        : "f"(__uint_as_float(r[j + 3])), "f"(__uint_as_float(r[j + 2])));
                    asm("mul.f16x2 %0, %1, %2;" : "=r"(hh) : "r"(hh), "r"(cf2));
                    asm("ex2.approx.f16x2 %0, %1;" : "=r"(e) : "r"(hh));
                    asm("add.f16x2 %0, %1, %2;" : "=r"(a1) : "r"(a1), "r"(e));
                }
                float2 f0 = __half22float2(*(__half2*)&a0);
                float2 f1 = __half22float2(*(__half2*)&a1);
                rowsum += (f0.x + f0.y) + (f1.x + f1.y);
            }
        } else {
            // diagonal tile: exact f32 path with masking
            const int dcol = rg - jb1 - half * 64;
            #pragma unroll
            for (int h = 0; h < 2; h++) {
                uint32_t r[32];
                LDTM_X32(r, taddr + h * 32);
                TC_WAIT_LD();
                float s0 = 0.f;
                #pragma unroll
                for (int j = 0; j < 32; j++) {
                    float e = ex2f(__uint_as_float(r[j]) * Cf);
                    if (j + h * 32 != dcol) s0 += e;
                }
                rowsum += s0;
            }
        }
        TC_FENCE_BEFORE();
    }

    atomicAdd(&d_S[rg], rowsum);

    __syncthreads();
    if (tid == 0) { MBAR_INVAL(sb + 8); MBAR_INVAL(sb + 16); }
    __syncthreads();
    if (w == 0) {
        asm volatile("tcgen05.relinquish_alloc_permit.cta_group::1.sync.aligned;");
        asm volatile("tcgen05.dealloc.cta_group::1.sync.aligned.b32 %0, 256;"
                     :: "r"(tmem));
    }
#else
    // ---------------- HMMA fallback (plain sm_103 pass; never runs on GB300) ------
    __nv_bfloat16* As = (__nv_bfloat16*)smem;
    __nv_bfloat16* Bs = As + BM * LDSTR;

    const int wid    = tid >> 5;
    const int lane   = tid & 31;
    const int g      = lane >> 2;
    const int q      = lane & 3;
    const int warp_m = wid & 3;
    const int warp_n = wid >> 2;

    for (int c = tid; c < BM * DD / 8; c += 256) {
        int row = c >> 4, c8 = c & 15;
        *(uint4*)(As + row * LDSTR + c8 * 8) =
            *(const uint4*)(d_zb + (size_t)(ibase + row) * DD + c8 * 8);
    }

    float rowsum[2][2] = {{0.f, 0.f}, {0.f, 0.f}};

    for (int jt = 0; jt < JT; ++jt) {
        const int jbase = j0 + jt * BN;
        __syncthreads();
        for (int c = tid; c < BN * DD / 8; c += 256) {
            int row = c >> 4, c8 = c & 15;
            *(uint4*)(Bs + row * LDSTR + c8 * 8) =
                *(const uint4*)(d_zb + (size_t)(jbase + row) * DD + c8 * 8);
        }
        __syncthreads();

        float acc[2][8][4];
        #pragma unroll
        for (int mf = 0; mf < 2; mf++)
            #pragma unroll
            for (int nf = 0; nf < 8; nf++)
                #pragma unroll
                for (int e = 0; e < 4; e++) acc[mf][nf][e] = 0.f;

        #pragma unroll
        for (int kk = 0; kk < 8; kk++) {
            const int kb = kk * 16;
            uint32_t a[2][4], b[8][2];
            #pragma unroll
            for (int mf = 0; mf < 2; mf++) {
                const __nv_bfloat16* pp =
                    As + (warp_m * 32 + mf * 16 + g) * LDSTR + kb + 2 * q;
                a[mf][0] = *(const uint32_t*)pp;
                a[mf][1] = *(const uint32_t*)(pp + 8 * LDSTR);
                a[mf][2] = *(const uint32_t*)(pp + 8);
                a[mf][3] = *(const uint32_t*)(pp + 8 * LDSTR + 8);
            }
            #pragma unroll
            for (int nf = 0; nf < 8; nf++) {
                const __nv_bfloat16* pp =
                    Bs + (warp_n * 64 + nf * 8 + g) * LDSTR + kb + 2 * q;
                b[nf][0] = *(const uint32_t*)pp;
                b[nf][1] = *(const uint32_t*)(pp + 8);
            }
            #pragma unroll
            for (int mf = 0; mf < 2; mf++)
                #pragma unroll
                for (int nf = 0; nf < 8; nf++)
                    mma16816(acc[mf][nf], a[mf], b[nf]);
        }

        #pragma unroll
        for (int mf = 0; mf < 2; mf++)
            #pragma unroll
            for (int nf = 0; nf < 8; nf++)
                #pragma unroll
                for (int e = 0; e < 4; e++) {
                    int rgl = ibase + warp_m * 32 + mf * 16 + g + ((e >> 1) << 3);
                    int cg  = jbase + warp_n * 64 + nf * 8 + q * 2 + (e & 1);
                    float ev = (rgl == cg) ? 0.f : __expf(acc[mf][nf][e] * 10.0f);
                    rowsum[mf][e >> 1] += ev;
                }
    }

    #pragma unroll
    for (int mf = 0; mf < 2; mf++)
        #pragma unroll
        for (int h = 0; h < 2; h++) {
            float s = rowsum[mf][h];
            s += __shfl_xor_sync(0xffffffffu, s, 1);
            s += __shfl_xor_sync(0xffffffffu, s, 2);
            if (q == 0)
                atomicAdd(&d_S[ibase + warp_m * 32 + mf * 16 + g + h * 8], s);
        }
#endif

    // -------- last-block final reduction (replaces separate reduce kernels) --------
    __shared__ double red[8];
    __shared__ int lastflag;
    __threadfence();
    __syncthreads();
    if (tid == 0) {
        unsigned v = atomicAdd(&d_count, 1u);
        lastflag = (v == NBLK - 1);
    }
    __syncthreads();
    if (lastflag) {
        __threadfence();
        double s = 0.0;
        for (int i = tid; i < NROWS; i += 256) s += (double)__logf(d_S[i]);
        for (int i = tid; i < NB;    i += 256) s -= 20.0 * (double)d_pos[i];
        #pragma unroll
        for (int o = 16; o; o >>= 1) s += __shfl_xor_sync(0xffffffffu, s, o);
        if ((tid & 31) == 0) red[tid >> 5] = s;
        __syncthreads();
        if (tid == 0) {
            double t2 = 0.0;
            #pragma unroll
            for (int u = 0; u < 8; u++) t2 += red[u];
            out[0] = (float)(t2 / (double)NROWS);
        }
    }
}

// ------------------------------------------------------------------ launch
extern "C" void kernel_launch(void* const* d_in, const int* in_sizes, int n_in,
                              void* d_out, int out_size) {
    const float* xi = (const float*)d_in[0];
    const float* xj = (const float*)d_in[1];
    float* out = (float*)d_out;

    cudaFuncSetAttribute(sim_kernel,
                         cudaFuncAttributeMaxDynamicSharedMemorySize, SMEM_TOT);

    normalize_kernel<<<NROWS / 8, 256>>>(xi, xj);
    pos_kernel<<<NB / 8, 256>>>();
    dim3 grid(NROWS / BM, JSPLIT);
    sim_kernel<<<grid, 256, SMEM_TOT>>>(out);
}

// round 9
// speedup vs baseline: 1.5088x; 1.0551x over previous
#include <cuda_runtime.h>
#include <cuda_bf16.h>
#include <cuda_fp16.h>
#include <stdint.h>

#define NB     4096
#define NROWS  8192
#define DD     128
#define BM     128
#define BN     128
#define JSPLIT 4
#define JT     (NROWS / JSPLIT / BN)   // 16
#define NBLK   ((NROWS / BM) * JSPLIT) // 256
#define LDSTR  136                      // fallback smem stride

// tcgen05 only exists in the arch-specific (sm_103a/sm_100a) compilation pass.
#if !defined(__CUDA_ARCH__) || defined(__CUDA_ARCH_FEAT_SM103_ALL) || \
    defined(__CUDA_ARCH_FEAT_SM100_ALL) || defined(__CUDA_ARCH_SPECIFIC__) || \
    defined(__CUDA_ARCH_FAMILY_SPECIFIC__)
#define HAS_TC 1
#else
#define HAS_TC 0
#endif

__device__ __align__(16) __nv_bfloat16  d_zb[NROWS * DD];
__device__ float        d_S  [NROWS];
__device__ float        d_pos[NB];
__device__ unsigned int d_count;

// ------------------------------------------------------------------ utils
__device__ __forceinline__ uint32_t smem_u32(const void* p) {
    uint32_t a;
    asm("{ .reg .u64 t; cvta.to.shared.u64 t, %1; cvt.u32.u64 %0, t; }"
        : "=r"(a) : "l"(p));
    return a;
}
__device__ __forceinline__ float ex2f(float x) {
    float y; asm("ex2.approx.ftz.f32 %0, %1;" : "=f"(y) : "f"(x)); return y;
}
__device__ __forceinline__ void cpasync16(uint32_t dst, const void* src) {
    asm volatile("cp.async.cg.shared.global [%0], [%1], 16;"
                 :: "r"(dst), "l"(src) : "memory");
}
#define CP_COMMIT() asm volatile("cp.async.commit_group;" ::: "memory")
#define CP_WAIT0()  asm volatile("cp.async.wait_group 0;" ::: "memory")

// ------------------------------------------------------------------ normalize + positives (+zero S/count)
// one warp per pair (xi_i, xj_i): both norms + dot in one pass
__global__ void normalize_kernel(const float* __restrict__ xi,
                                 const float* __restrict__ xj) {
    int t = blockIdx.x * blockDim.x + threadIdx.x;
    if (t < NROWS) d_S[t] = 0.0f;
    if (t == 0) d_count = 0u;
    int pair = t >> 5;
    int lane = threadIdx.x & 31;
    if (pair >= NB) return;
    float4 a = ((const float4*)(xi + (size_t)pair * DD))[lane];
    float4 b = ((const float4*)(xj + (size_t)pair * DD))[lane];
    float saa = a.x*a.x + a.y*a.y + a.z*a.z + a.w*a.w;
    float sbb = b.x*b.x + b.y*b.y + b.z*b.z + b.w*b.w;
    float sab = a.x*b.x + a.y*b.y + a.z*b.z + a.w*b.w;
    #pragma unroll
    for (int o = 16; o; o >>= 1) {
        saa += __shfl_xor_sync(0xffffffffu, saa, o);
        sbb += __shfl_xor_sync(0xffffffffu, sbb, o);
        sab += __shfl_xor_sync(0xffffffffu, sab, o);
    }
    float inva = 1.0f / fmaxf(sqrtf(saa), 1e-12f);
    float invb = 1.0f / fmaxf(sqrtf(sbb), 1e-12f);
    __nv_bfloat162* za = (__nv_bfloat162*)(d_zb + (size_t)pair * DD);
    __nv_bfloat162* zb = (__nv_bfloat162*)(d_zb + (size_t)(pair + NB) * DD);
    za[lane*2 + 0] = __floats2bfloat162_rn(a.x*inva, a.y*inva);
    za[lane*2 + 1] = __floats2bfloat162_rn(a.z*inva, a.w*inva);
    zb[lane*2 + 0] = __floats2bfloat162_rn(b.x*invb, b.y*invb);
    zb[lane*2 + 1] = __floats2bfloat162_rn(b.z*invb, b.w*invb);
    if (lane == 0) d_pos[pair] = sab * inva * invb;
}

// ================================================================== tcgen05 path
#if HAS_TC
#define DESC_BASE ((2ull << 61) | (1ull << 46) | (64ull << 32) | (1ull << 16))
__device__ __forceinline__ uint64_t make_desc(uint32_t addr) {
    return DESC_BASE | ((uint64_t)(addr >> 4) & 0x3FFF);
}
// idesc kind::f16: dtype=F32, a=BF16, b=BF16 (K-major), N=128, M=128 (proven)
#define MMA_IDESC 0x8200490u

__device__ __forceinline__ void mma_f16_ss(uint32_t d, uint64_t a, uint64_t b,
                                           uint32_t en) {
    asm volatile(
        "{\n\t.reg .pred p;\n\t"
        "setp.ne.u32 p, %4, 0;\n\t"
        "tcgen05.mma.cta_group::1.kind::f16 [%0], %1, %2, %3, {%5,%5,%5,%5}, p;\n\t}"
        :: "r"(d), "l"(a), "l"(b), "r"(MMA_IDESC), "r"(en), "r"(0u) : "memory");
}

#define MBAR_INIT(a)   asm volatile("mbarrier.init.shared.b64 [%0], 1;" :: "r"(a) : "memory")
#define MBAR_INVAL(a)  asm volatile("mbarrier.inval.shared.b64 [%0];"   :: "r"(a) : "memory")
#define TC_COMMIT(a)   asm volatile("tcgen05.commit.cta_group::1.mbarrier::arrive::one.shared::cluster.b64 [%0];" :: "r"(a) : "memory")
#define TC_FENCE_AFTER()  asm volatile("tcgen05.fence::after_thread_sync;"  ::: "memory")
#define TC_FENCE_BEFORE() asm volatile("tcgen05.fence::before_thread_sync;" ::: "memory")
#define TC_WAIT_LD()      asm volatile("tcgen05.wait::ld.sync.aligned;"     ::: "memory")
#define FENCE_ASYNC()     asm volatile("fence.proxy.async.shared::cta;"     ::: "memory")

__device__ __forceinline__ void mbar_wait(uint32_t mbar, uint32_t parity) {
    uint32_t done;
    asm volatile(
        "{\n\t.reg .pred p;\n\t"
        "mbarrier.try_wait.parity.acquire.cta.shared::cta.b64 p, [%1], %2;\n\t"
        "selp.b32 %0, 1, 0, p;\n\t}"
        : "=r"(done) : "r"(mbar), "r"(parity) : "memory");
    if (!done) {
        asm volatile(
            "{\n\t.reg .pred P1;\n\t"
            "WL_%=:\n\t"
            "mbarrier.try_wait.parity.acquire.cta.shared::cta.b64 P1, [%0], %1, 0x989680;\n\t"
            "@P1 bra.uni WD_%=;\n\t"
            "bra.uni WL_%=;\n\t"
            "WD_%=:\n\t}"
            :: "r"(mbar), "r"(parity) : "memory");
    }
}

#define LDTM_X32(r, a) \
    asm volatile("tcgen05.ld.sync.aligned.32x32b.x32.b32 " \
        "{%0,%1,%2,%3,%4,%5,%6,%7,%8,%9,%10,%11,%12,%13,%14,%15," \
        "%16,%17,%18,%19,%20,%21,%22,%23,%24,%25,%26,%27,%28,%29,%30,%31}, [%32];" \
        : "=r"((r)[0]),"=r"((r)[1]),"=r"((r)[2]),"=r"((r)[3]), \
          "=r"((r)[4]),"=r"((r)[5]),"=r"((r)[6]),"=r"((r)[7]), \
          "=r"((r)[8]),"=r"((r)[9]),"=r"((r)[10]),"=r"((r)[11]), \
          "=r"((r)[12]),"=r"((r)[13]),"=r"((r)[14]),"=r"((r)[15]), \
          "=r"((r)[16]),"=r"((r)[17]),"=r"((r)[18]),"=r"((r)[19]), \
          "=r"((r)[20]),"=r"((r)[21]),"=r"((r)[22]),"=r"((r)[23]), \
          "=r"((r)[24]),"=r"((r)[25]),"=r"((r)[26]),"=r"((r)[27]), \
          "=r"((r)[28]),"=r"((r)[29]),"=r"((r)[30]),"=r"((r)[31]) \
        : "r"(a))
#endif  // HAS_TC

// blocked-atom SW128 byte offset for (row, 16B-chunk) of a 128x128 bf16 tile
__device__ __forceinline__ uint32_t tile_off(int row, int c16) {
    uint32_t byte = (uint32_t)(((row >> 3) + ((c16 >> 3) << 4)) * 1024
                               + (row & 7) * 128 + (c16 & 7) * 16);
    return byte ^ ((byte >> 3) & 0x70);
}

#if !HAS_TC
__device__ __forceinline__ void mma16816(float c[4], const uint32_t a[4],
                                         const uint32_t b[2]) {
    asm volatile(
        "mma.sync.aligned.m16n8k16.row.col.f32.bf16.bf16.f32 "
        "{%0,%1,%2,%3}, {%4,%5,%6,%7}, {%8,%9}, {%0,%1,%2,%3};\n"
        : "+f"(c[0]), "+f"(c[1]), "+f"(c[2]), "+f"(c[3])
        : "r"(a[0]), "r"(a[1]), "r"(a[2]), "r"(a[3]), "r"(b[0]), "r"(b[1]));
}
#endif

// smem: [0] tmem ptr, [8..24) mbar[2], [1024) A 32KB, [+32K) B0, B1
#define S_OFF_A   1024
#define S_OFF_B0  (S_OFF_A + 32768)
#define SMEM_TOT  (S_OFF_B0 + 2 * 32768)

__global__ void __launch_bounds__(256, 2) sim_kernel(float* __restrict__ out) {
    extern __shared__ __align__(1024) char smem[];
    const int tid   = threadIdx.x;
    const int ibase = blockIdx.x * BM;
    const int j0    = blockIdx.y * (NROWS / JSPLIT);

#if HAS_TC
    const uint32_t sb = smem_u32(smem);
    const int w    = tid >> 5, lane = tid & 31;
    const int sp   = w & 3, half = w >> 2;
    const int rg   = ibase + sp * 32 + lane;
    const float Cf = 14.4269504088896340737f;   // (1/T) * log2(e)
    uint32_t cf2;
    { __half2 h2 = __float2half2_rn(Cf); cf2 = *(uint32_t*)&h2; }
    uint32_t z16;
    { __half2 z2 = __float2half2_rn(0.f); z16 = *(uint32_t*)&z2; }

    // start A + B0 loads immediately (cp.async, no registers held)
    #pragma unroll
    for (int u = 0; u < 8; u++) {
        int c = tid + u * 256;
        int row = c >> 4, c16 = c & 15;
        uint32_t so = tile_off(row, c16);
        cpasync16(sb + S_OFF_A  + so, d_zb + (size_t)(ibase + row) * DD + c16 * 8);
        cpasync16(sb + S_OFF_B0 + so, d_zb + (size_t)(j0    + row) * DD + c16 * 8);
    }
    CP_COMMIT();

    if (w == 0)
        asm volatile("tcgen05.alloc.cta_group::1.sync.aligned.shared::cta.b32 [%0], 256;"
                     :: "r"(sb) : "memory");
    if (tid == 0) { MBAR_INIT(sb + 8); MBAR_INIT(sb + 16); }

    CP_WAIT0();
    FENCE_ASYNC();
    __syncthreads();
    uint32_t tmem;
    asm volatile("ld.shared.b32 %0, [%1];" : "=r"(tmem) : "r"(sb));
    const uint64_t a_desc = make_desc(sb + S_OFF_A);

    // MMA(0) on B0
    if (tid == 0) {
        const uint64_t b_desc = make_desc(sb + S_OFF_B0);
        #pragma unroll
        for (int k = 0; k < 8; k++) {
            uint32_t off = (k < 4) ? 2u * k : 1024u + 2u * (k - 4);
            mma_f16_ss(tmem, a_desc + off, b_desc + off, k > 0);
        }
        TC_COMMIT(sb + 8);
    }
    // prefetch B1 into buf1
    #pragma unroll
    for (int u = 0; u < 8; u++) {
        int c = tid + u * 256;
        int row = c >> 4, c16 = c & 15;
        cpasync16(sb + S_OFF_B0 + 32768 + tile_off(row, c16),
                  d_zb + (size_t)(j0 + BN + row) * DD + c16 * 8);
    }
    CP_COMMIT();

    float rowsum = 0.0f;

    for (int jt = 1; jt <= JT; ++jt) {
        const int p = jt & 1, q = p ^ 1;

        // B(jt) ready in buf p
        if (jt < JT) { CP_WAIT0(); FENCE_ASYNC(); }
        __syncthreads();   // also: epilogue of tile jt-2 (used D[p]) finished

        // issue MMA(jt) into D[p]
        if (jt < JT && tid == 0) {
            const uint64_t b_desc = make_desc(sb + S_OFF_B0 + p * 32768);
            const uint32_t dtm = tmem + p * 128;
            #pragma unroll
            for (int k = 0; k < 8; k++) {
                uint32_t off = (k < 4) ? 2u * k : 1024u + 2u * (k - 4);
                mma_f16_ss(dtm, a_desc + off, b_desc + off, k > 0);
            }
            TC_COMMIT(sb + 8 + p * 8);
        }

        // MMA(jt-1) done -> D[q] ready, buf q free
        mbar_wait(sb + 8 + q * 8, ((jt - 1) >> 1) & 1);
        TC_FENCE_AFTER();

        // issue BOTH LDTM chunks, then cover their latency with cp.async issue
        const uint32_t taddr = tmem + q * 128 + ((uint32_t)sp << 21) + half * 64;
        uint32_t r0[32], r1[32];
        LDTM_X32(r0, taddr);
        LDTM_X32(r1, taddr + 32);

        // prefetch B(jt+1) into freed buf q (rides under LDTM latency)
        if (jt + 1 < JT) {
            const int jb = j0 + (jt + 1) * BN;
            #pragma unroll
            for (int u = 0; u < 8; u++) {
                int c = tid + u * 256;
                int row = c >> 4, c16 = c & 15;
                cpasync16(sb + S_OFF_B0 + q * 32768 + tile_off(row, c16),
                          d_zb + (size_t)(jb + row) * DD + c16 * 8);
            }
            CP_COMMIT();
        }

        TC_WAIT_LD();

        const int jb1 = j0 + (jt - 1) * BN;
        if (jb1 != ibase) {
            uint32_t a0 = z16, a1 = z16, a2 = z16, a3 = z16;
            #pragma unroll
            for (int j = 0; j < 32; j += 4) {
                uint32_t hh, e;
                asm("cvt.rn.f16x2.f32 %0, %1, %2;" : "=r"(hh)
                    : "f"(__uint_as_float(r0[j + 1])), "f"(__uint_as_float(r0[j])));
                asm("mul.f16x2 %0, %1, %2;" : "=r"(hh) : "r"(hh), "r"(cf2));
                asm("ex2.approx.f16x2 %0, %1;" : "=r"(e) : "r"(hh));
                asm("add.f16x2 %0, %1, %2;" : "=r"(a0) : "r"(a0), "r"(e));
                asm("cvt.rn.f16x2.f32 %0, %1, %2;" : "=r"(hh)
                    : "f"(__uint_as_float(r0[j + 3])), "f"(__uint_as_float(r0[j + 2])));
                asm("mul.f16x2 %0, %1, %2;" : "=r"(hh) : "r"(hh), "r"(cf2));
                asm("ex2.approx.f16x2 %0, %1;" : "=r"(e) : "r"(hh));
                asm("add.f16x2 %0, %1, %2;" : "=r"(a1) : "r"(a1), "r"(e));
                asm("cvt.rn.f16x2.f32 %0, %1, %2;" : "=r"(hh)
                    : "f"(__uint_as_float(r1[j + 1])), "f"(__uint_as_float(r1[j])));
                asm("mul.f16x2 %0, %1, %2;" : "=r"(hh) : "r"(hh), "r"(cf2));
                asm("ex2.approx.f16x2 %0, %1;" : "=r"(e) : "r"(hh));
                asm("add.f16x2 %0, %1, %2;" : "=r"(a2) : "r"(a2), "r"(e));
                asm("cvt.rn.f16x2.f32 %0, %1, %2;" : "=r"(hh)
                    : "f"(__uint_as_float(r1[j + 3])), "f"(__uint_as_float(r1[j + 2])));
                asm("mul.f16x2 %0, %1, %2;" : "=r"(hh) : "r"(hh), "r"(cf2));
                asm("ex2.approx.f16x2 %0, %1;" : "=r"(e) : "r"(hh));
                asm("add.f16x2 %0, %1, %2;" : "=r"(a3) : "r"(a3), "r"(e));
            }
            float2 f0 = __half22float2(*(__half2*)&a0);
            float2 f1 = __half22float2(*(__half2*)&a1);
            float2 f2 = __half22float2(*(__half2*)&a2);
            float2 f3 = __half22float2(*(__half2*)&a3);
            rowsum += ((f0.x + f0.y) + (f1.x + f1.y))
                    + ((f2.x + f2.y) + (f3.x + f3.y));
        } else {
            // diagonal tile: exact f32 path with masking
            const int dcol = rg - jb1 - half * 64;
            float s0 = 0.f, s1 = 0.f;
            #pragma unroll
            for (int j = 0; j < 32; j++) {
                float e = ex2f(__uint_as_float(r0[j]) * Cf);
                if (j != dcol) s0 += e;
            }
            #pragma unroll
            for (int j = 0; j < 32; j++) {
                float e = ex2f(__uint_as_float(r1[j]) * Cf);
                if (j + 32 != dcol) s1 += e;
            }
            rowsum += s0 + s1;
        }
        TC_FENCE_BEFORE();
    }

    atomicAdd(&d_S[rg], rowsum);

    __syncthreads();
    if (tid == 0) { MBAR_INVAL(sb + 8); MBAR_INVAL(sb + 16); }
    __syncthreads();
    if (w == 0) {
        asm volatile("tcgen05.relinquish_alloc_permit.cta_group::1.sync.aligned;");
        asm volatile("tcgen05.dealloc.cta_group::1.sync.aligned.b32 %0, 256;"
                     :: "r"(tmem));
    }
#else
    // ---------------- HMMA fallback (plain sm_103 pass; never runs on GB300) ------
    __nv_bfloat16* As = (__nv_bfloat16*)smem;
    __nv_bfloat16* Bs = As + BM * LDSTR;

    const int wid    = tid >> 5;
    const int lane   = tid & 31;
    const int g      = lane >> 2;
    const int q      = lane & 3;
    const int warp_m = wid & 3;
    const int warp_n = wid >> 2;

    for (int c = tid; c < BM * DD / 8; c += 256) {
        int row = c >> 4, c8 = c & 15;
        *(uint4*)(As + row * LDSTR + c8 * 8) =
            *(const uint4*)(d_zb + (size_t)(ibase + row) * DD + c8 * 8);
    }

    float rowsum[2][2] = {{0.f, 0.f}, {0.f, 0.f}};

    for (int jt = 0; jt < JT; ++jt) {
        const int jbase = j0 + jt * BN;
        __syncthreads();
        for (int c = tid; c < BN * DD / 8; c += 256) {
            int row = c >> 4, c8 = c & 15;
            *(uint4*)(Bs + row * LDSTR + c8 * 8) =
                *(const uint4*)(d_zb + (size_t)(jbase + row) * DD + c8 * 8);
        }
        __syncthreads();

        float acc[2][8][4];
        #pragma unroll
        for (int mf = 0; mf < 2; mf++)
            #pragma unroll
            for (int nf = 0; nf < 8; nf++)
                #pragma unroll
                for (int e = 0; e < 4; e++) acc[mf][nf][e] = 0.f;

        #pragma unroll
        for (int kk = 0; kk < 8; kk++) {
            const int kb = kk * 16;
            uint32_t a[2][4], b[8][2];
            #pragma unroll
            for (int mf = 0; mf < 2; mf++) {
                const __nv_bfloat16* pp =
                    As + (warp_m * 32 + mf * 16 + g) * LDSTR + kb + 2 * q;
                a[mf][0] = *(const uint32_t*)pp;
                a[mf][1] = *(const uint32_t*)(pp + 8 * LDSTR);
                a[mf][2] = *(const uint32_t*)(pp + 8);
                a[mf][3] = *(const uint32_t*)(pp + 8 * LDSTR + 8);
            }
            #pragma unroll
            for (int nf = 0; nf < 8; nf++) {
                const __nv_bfloat16* pp =
                    Bs + (warp_n * 64 + nf * 8 + g) * LDSTR + kb + 2 * q;
                b[nf][0] = *(const uint32_t*)pp;
                b[nf][1] = *(const uint32_t*)(pp + 8);
            }
            #pragma unroll
            for (int mf = 0; mf < 2; mf++)
                #pragma unroll
                for (int nf = 0; nf < 8; nf++)
                    mma16816(acc[mf][nf], a[mf], b[nf]);
        }

        #pragma unroll
        for (int mf = 0; mf < 2; mf++)
            #pragma unroll
            for (int nf = 0; nf < 8; nf++)
                #pragma unroll
                for (int e = 0; e < 4; e++) {
                    int rgl = ibase + warp_m * 32 + mf * 16 + g + ((e >> 1) << 3);
                    int cg  = jbase + warp_n * 64 + nf * 8 + q * 2 + (e & 1);
                    float ev = (rgl == cg) ? 0.f : __expf(acc[mf][nf][e] * 10.0f);
                    rowsum[mf][e >> 1] += ev;
                }
    }

    #pragma unroll
    for (int mf = 0; mf < 2; mf++)
        #pragma unroll
        for (int h = 0; h < 2; h++) {
            float s = rowsum[mf][h];
            s += __shfl_xor_sync(0xffffffffu, s, 1);
            s += __shfl_xor_sync(0xffffffffu, s, 2);
            if (q == 0)
                atomicAdd(&d_S[ibase + warp_m * 32 + mf * 16 + g + h * 8], s);
        }
#endif

    // -------- last-block final reduction (replaces separate reduce kernels) --------
    __shared__ double red[8];
    __shared__ int lastflag;
    __threadfence();
    __syncthreads();
    if (tid == 0) {
        unsigned v = atomicAdd(&d_count, 1u);
        lastflag = (v == NBLK - 1);
    }
    __syncthreads();
    if (lastflag) {
        __threadfence();
        double s = 0.0;
        for (int i = tid; i < NROWS; i += 256) s += (double)__logf(d_S[i]);
        for (int i = tid; i < NB;    i += 256) s -= 20.0 * (double)d_pos[i];
        #pragma unroll
        for (int o = 16; o; o >>= 1) s += __shfl_xor_sync(0xffffffffu, s, o);
        if ((tid & 31) == 0) red[tid >> 5] = s;
        __syncthreads();
        if (tid == 0) {
            double t2 = 0.0;
            #pragma unroll
            for (int u = 0; u < 8; u++) t2 += red[u];
            out[0] = (float)(t2 / (double)NROWS);
        }
    }
}

// ------------------------------------------------------------------ launch
extern "C" void kernel_launch(void* const* d_in, const int* in_sizes, int n_in,
                              void* d_out, int out_size) {
    const float* xi = (const float*)d_in[0];
    const float* xj = (const float*)d_in[1];
    float* out = (float*)d_out;

    cudaFuncSetAttribute(sim_kernel,
                         cudaFuncAttributeMaxDynamicSharedMemorySize, SMEM_TOT);

    normalize_kernel<<<NB / 8, 256>>>(xi, xj);   // 4096 pairs, 8 warps/block
    dim3 grid(NROWS / BM, JSPLIT);
    sim_kernel<<<grid, 256, SMEM_TOT>>>(out);
}